// round 10
// baseline (speedup 1.0000x reference)
#include <cuda_runtime.h>
#include <cuda_fp16.h>
#include <cuda_bf16.h>

#define N_NODES   100000
#define N_EDGES   3200000
#define IN_DIM    128
#define HID       64
#define OUT_DIM   128
#define N_GRAPHS  8
#define PAD       96                  // padded CSR row stride (Poisson(32), 11 sigma)
#define WFIX      1048576.0f          // 2^20 fixed-point scale for weights

// ---------------- scratch (static __device__, no allocs) ----------------
__device__ unsigned long long g_pk[N_NODES];            // {count:24 | wsum.20fix:40}
__device__ float g_dinv[N_NODES];
__device__ int   g_cnt_e[N_NODES];
__device__ int   g_epos[N_EDGES];                       // within-row position per edge
__device__ __align__(16) int2  g_edgeP[N_NODES * PAD];  // padded CSR {src, norm bits}
__device__ __align__(16) __half g_bufH[N_NODES * HID];  // fp16 features for gathers
__device__ __align__(16) float g_bufA[N_NODES * HID];
__device__ __align__(16) float g_bufB[N_NODES * HID];
__device__ float g_pool[N_GRAPHS * HID];
__device__ float g_cnt[N_GRAPHS];

// ---------------- init: packed (count=0, wsum=1.0 self loop); pool=0 ----------------
__global__ void k_init0(int n) {
    int i = blockIdx.x * blockDim.x + threadIdx.x;
    if (i < n) g_pk[i] = (unsigned long long)(1u << 20);   // weight 1.0 fixed
    if (i < N_GRAPHS * HID) g_pool[i] = 0.0f;
    if (i < N_GRAPHS) g_cnt[i] = 0.0f;
}

// ---------------- FUSED: gemm1 (blocks < GB) || edge count (blocks >= GB) --------
// gemm1: bufH[n x 64] = x[n x 128] @ W1 (fp16 out). count: packed 64-bit atomic.
__global__ void k_gemm1_count(const float* __restrict__ X, const float* __restrict__ W,
                              __half* __restrict__ Y,
                              const int* __restrict__ dst, const float* __restrict__ w,
                              int n, int E, int GB) {
    __shared__ float Xs[128 * 33];
    __shared__ float Ws[32 * 64];
    int t = threadIdx.x;

    if (blockIdx.x >= GB) {
        // -------- count role --------
        int e = (blockIdx.x - GB) * 256 + t;
        if (e < E) {
            int d = dst[e];
            unsigned int wf = __float2uint_rn(w[e] * WFIX);
            unsigned long long inc = (1ULL << 40) | (unsigned long long)wf;
            unsigned long long old = atomicAdd(&g_pk[d], inc);
            g_epos[e] = (int)(old >> 40);
        }
        return;
    }

    // -------- gemm role (K = IN_DIM = 128) --------
    int row0 = blockIdx.x * 128;
    int tx = t & 7;
    int ty = t >> 3;
    int c0 = tx * 8;
    int r0 = ty * 4;

    float acc[4][8];
#pragma unroll
    for (int i = 0; i < 4; i++)
#pragma unroll
        for (int j = 0; j < 8; j++) acc[i][j] = 0.0f;

    for (int kc = 0; kc < IN_DIM; kc += 32) {
#pragma unroll
        for (int i = t; i < 32 * 64; i += 256) Ws[i] = W[(kc + (i >> 6)) * 64 + (i & 63)];
#pragma unroll
        for (int i = t; i < 128 * 32; i += 256) {
            int r = i >> 5, k = i & 31;
            int gr = row0 + r;
            Xs[r * 33 + k] = (gr < n) ? X[gr * IN_DIM + kc + k] : 0.0f;
        }
        __syncthreads();

#pragma unroll
        for (int k = 0; k < 32; k++) {
            float xv[4];
#pragma unroll
            for (int i = 0; i < 4; i++) xv[i] = Xs[(r0 + i) * 33 + k];
            float4 w0 = *(const float4*)&Ws[k * 64 + c0];
            float4 w1 = *(const float4*)&Ws[k * 64 + c0 + 4];
            float wv[8] = {w0.x, w0.y, w0.z, w0.w, w1.x, w1.y, w1.z, w1.w};
#pragma unroll
            for (int i = 0; i < 4; i++)
#pragma unroll
                for (int j = 0; j < 8; j++) acc[i][j] += xv[i] * wv[j];
        }
        __syncthreads();
    }

#pragma unroll
    for (int i = 0; i < 4; i++) {
        int row = row0 + r0 + i;
        if (row < n) {
            __half2 h[4];
#pragma unroll
            for (int j = 0; j < 4; j++)
                h[j] = __floats2half2_rn(acc[i][2 * j], acc[i][2 * j + 1]);
            *(uint4*)(Y + row * 64 + c0) = *(uint4*)h;
        }
    }
}

// ---------------- prep: unpack pk -> dinv + cnt ----------------
__global__ void k_prep(int n) {
    int i = blockIdx.x * blockDim.x + threadIdx.x;
    if (i >= n) return;
    unsigned long long pk = g_pk[i];
    int c = (int)(pk >> 40);
    float deg = (float)(pk & ((1ULL << 40) - 1)) * (1.0f / WFIX);
    g_dinv[i] = rsqrtf(deg);
    g_cnt_e[i] = c;
}

// ---------------- fill padded CSR (by dst), atomic-free, fused norm ----------------
__global__ void k_fill(const int* __restrict__ src, const int* __restrict__ dst,
                       const float* __restrict__ w, int E) {
    int e = blockIdx.x * blockDim.x + threadIdx.x;
    if (e >= E) return;
    int s = src[e];
    int d = dst[e];
    int p = g_epos[e];
    p = (p < PAD) ? p : (PAD - 1);        // defensive clamp (P ~ 0)
    float norm = g_dinv[s] * w[e] * g_dinv[d];
    g_edgeP[d * PAD + p] = make_int2(s, __float_as_int(norm));
}

// ---------------- register-tiled GEMM (conv2): fp16 out, relu(X+b) in ----------------
__global__ void k_gemm2(const float* __restrict__ X, const float* __restrict__ W,
                        const float* __restrict__ bias, __half* __restrict__ Y, int n) {
    __shared__ float Xs[128 * 33];
    __shared__ float Ws[32 * 64];

    int t = threadIdx.x;
    int row0 = blockIdx.x * 128;
    int tx = t & 7;
    int ty = t >> 3;
    int c0 = tx * 8;
    int r0 = ty * 4;

    float acc[4][8];
#pragma unroll
    for (int i = 0; i < 4; i++)
#pragma unroll
        for (int j = 0; j < 8; j++) acc[i][j] = 0.0f;

    for (int kc = 0; kc < HID; kc += 32) {
#pragma unroll
        for (int i = t; i < 32 * 64; i += 256) Ws[i] = W[(kc + (i >> 6)) * 64 + (i & 63)];
#pragma unroll
        for (int i = t; i < 128 * 32; i += 256) {
            int r = i >> 5, k = i & 31;
            int gr = row0 + r;
            float v = (gr < n) ? X[gr * HID + kc + k] : 0.0f;
            v = fmaxf(v + __ldg(&bias[kc + k]), 0.0f);
            Xs[r * 33 + k] = v;
        }
        __syncthreads();

#pragma unroll
        for (int k = 0; k < 32; k++) {
            float xv[4];
#pragma unroll
            for (int i = 0; i < 4; i++) xv[i] = Xs[(r0 + i) * 33 + k];
            float4 w0 = *(const float4*)&Ws[k * 64 + c0];
            float4 w1 = *(const float4*)&Ws[k * 64 + c0 + 4];
            float wv[8] = {w0.x, w0.y, w0.z, w0.w, w1.x, w1.y, w1.z, w1.w};
#pragma unroll
            for (int i = 0; i < 4; i++)
#pragma unroll
                for (int j = 0; j < 8; j++) acc[i][j] += xv[i] * wv[j];
        }
        __syncthreads();
    }

#pragma unroll
    for (int i = 0; i < 4; i++) {
        int row = row0 + r0 + i;
        if (row < n) {
            __half2 h[4];
#pragma unroll
            for (int j = 0; j < 4; j++)
                h[j] = __floats2half2_rn(acc[i][2 * j], acc[i][2 * j + 1]);
            *(uint4*)(Y + row * 64 + c0) = *(uint4*)h;
        }
    }
}

// ---------------- gather conv, fp16 H: OUT[d] = dinv^2*H[d] + sum norm*H[src] ----
// warp per node: 8 feature lanes (8 halfs = 16B each) x 4 edge slots; padded CSR.
__global__ void k_gather_h(const __half* __restrict__ H, float* __restrict__ OUT, int n) {
    int t = threadIdx.x;
    int fl   = t & 7;             // feature lane: halfs [fl*8, fl*8+8)
    int slot = (t >> 3) & 3;      // edge slot 0..3
    int node = blockIdx.x * 8 + (t >> 5);
    if (node >= n) return;

    const uint4* Hp = (const uint4*)H;   // 8 uint4 per row

    float f[8];
#pragma unroll
    for (int j = 0; j < 8; j++) f[j] = 0.0f;

    if (slot == 0) {
        float dv = g_dinv[node];
        float s2 = dv * dv;
        uint4 u = Hp[node * 8 + fl];
        const __half2* hp = (const __half2*)&u;
#pragma unroll
        for (int j = 0; j < 4; j++) {
            float2 v = __half22float2(hp[j]);
            f[2 * j]     = s2 * v.x;
            f[2 * j + 1] = s2 * v.y;
        }
    }

    int beg = node * PAD;
    int end = beg + g_cnt_e[node];
    int e = beg + slot;
    for (; e + 4 < end; e += 8) {
        int2 e0 = g_edgeP[e];
        int2 e1 = g_edgeP[e + 4];
        uint4 u0 = Hp[e0.x * 8 + fl];
        uint4 u1 = Hp[e1.x * 8 + fl];
        float n0 = __int_as_float(e0.y);
        float n1 = __int_as_float(e1.y);
        const __half2* h0 = (const __half2*)&u0;
        const __half2* h1 = (const __half2*)&u1;
#pragma unroll
        for (int j = 0; j < 4; j++) {
            float2 v0 = __half22float2(h0[j]);
            float2 v1 = __half22float2(h1[j]);
            f[2 * j]     += n0 * v0.x + n1 * v1.x;
            f[2 * j + 1] += n0 * v0.y + n1 * v1.y;
        }
    }
    for (; e < end; e += 4) {
        int2 e0 = g_edgeP[e];
        uint4 u0 = Hp[e0.x * 8 + fl];
        float n0 = __int_as_float(e0.y);
        const __half2* h0 = (const __half2*)&u0;
#pragma unroll
        for (int j = 0; j < 4; j++) {
            float2 v0 = __half22float2(h0[j]);
            f[2 * j]     += n0 * v0.x;
            f[2 * j + 1] += n0 * v0.y;
        }
    }

    // reduce across the 4 edge slots (xor 8, xor 16)
#pragma unroll
    for (int off = 8; off < 32; off <<= 1)
#pragma unroll
        for (int j = 0; j < 8; j++)
            f[j] += __shfl_xor_sync(0xffffffffu, f[j], off);

    if (slot == 0) {
        float4 o0 = {f[0], f[1], f[2], f[3]};
        float4 o1 = {f[4], f[5], f[6], f[7]};
        *(float4*)&OUT[node * 64 + fl * 8]     = o0;
        *(float4*)&OUT[node * 64 + fl * 8 + 4] = o1;
    }
}

// ---------------- pool: two-stage segment sum over batch ids ----------------
#define POOL_NB 512
__global__ void k_pool(const float* __restrict__ AGG,
                       const int* __restrict__ batch, int n) {
    __shared__ float acc[N_GRAPHS][HID];
    __shared__ float scnt[N_GRAPHS];
    for (int i = threadIdx.x; i < N_GRAPHS * HID; i += 256)
        acc[i / HID][i % HID] = 0.f;
    if (threadIdx.x < N_GRAPHS) scnt[threadIdx.x] = 0.f;
    __syncthreads();

    int c  = threadIdx.x & 63;
    int nl = threadIdx.x >> 6;
    int base = blockIdx.x * POOL_NB;
    int lim = min(base + POOL_NB, n);
    for (int i = base + nl; i < lim; i += 4) {
        int b = batch[i];
        atomicAdd(&acc[b][c], AGG[i * 64 + c]);
        if (c == 0) atomicAdd(&scnt[b], 1.0f);
    }
    __syncthreads();
    for (int i = threadIdx.x; i < N_GRAPHS * HID; i += 256)
        atomicAdd(&g_pool[i], acc[i / HID][i % HID]);
    if (threadIdx.x < N_GRAPHS) atomicAdd(&g_cnt[threadIdx.x], scnt[threadIdx.x]);
}

// ---------------- final: out[g][o] = (pool[g]/cnt[g] + b2) @ Wfc + bfc ----------------
__global__ void k_final(const float* __restrict__ b2, const float* __restrict__ Wfc,
                        const float* __restrict__ bfc, float* __restrict__ out) {
    __shared__ float P[N_GRAPHS][HID];
    for (int i = threadIdx.x; i < N_GRAPHS * HID; i += 128) {
        int g = i / HID, c = i % HID;
        float cnt = fmaxf(g_cnt[g], 1.0f);
        P[g][c] = g_pool[i] / cnt + b2[c];
    }
    __syncthreads();
    int o = threadIdx.x;   // 128 threads
    for (int g = 0; g < N_GRAPHS; g++) {
        float s = bfc[o];
#pragma unroll
        for (int c = 0; c < HID; c++)
            s += P[g][c] * Wfc[c * OUT_DIM + o];
        out[g * OUT_DIM + o] = s;
    }
}

// ---------------- launcher ----------------
extern "C" void kernel_launch(void* const* d_in, const int* in_sizes, int n_in,
                              void* d_out, int out_size) {
    const float* x   = (const float*)d_in[0];
    const int*   ei  = (const int*)d_in[1];     // int64 inputs arrive as int32
    const float* ew  = (const float*)d_in[2];
    const int*   bat = (const int*)d_in[3];
    const float* W1  = (const float*)d_in[4];
    const float* b1  = (const float*)d_in[5];
    const float* W2  = (const float*)d_in[6];
    const float* b2  = (const float*)d_in[7];
    const float* Wfc = (const float*)d_in[8];
    const float* bfc = (const float*)d_in[9];
    float* out = (float*)d_out;

    int n = in_sizes[0] / IN_DIM;      // 100000
    int E = in_sizes[2];               // 3200000
    const int* src = ei;
    const int* dst = ei + E;

    float *bufA, *bufB;
    __half* bufH;
    cudaGetSymbolAddress((void**)&bufA, g_bufA);
    cudaGetSymbolAddress((void**)&bufB, g_bufB);
    cudaGetSymbolAddress((void**)&bufH, g_bufH);

    int gE = (E + 255) / 256;          // 12500
    int gN = (n + 255) / 256;
    int GB = (n + 127) / 128;          // 782 gemm blocks

    // ---- init, then fused gemm1 || edge-count ----
    k_init0<<<gN, 256>>>(n);
    k_gemm1_count<<<GB + gE, 256>>>(x, W1, bufH, dst, ew, n, E, GB);
    k_prep<<<gN, 256>>>(n);
    k_fill<<<gE, 256>>>(src, dst, ew, E);

    // ---- conv1 gather: agg1 -> bufB (fp32) ----
    k_gather_h<<<(n + 7) / 8, 256>>>(bufH, bufB, n);

    // ---- conv2: h2 = relu(agg1 + b1) @ W2 -> bufH (fp16) ; agg2 -> bufA ----
    k_gemm2<<<GB, 256>>>(bufB, W2, b1, bufH, n);
    k_gather_h<<<(n + 7) / 8, 256>>>(bufH, bufA, n);

    // ---- pool (b2 folded into final) + fc ----
    k_pool<<<(n + POOL_NB - 1) / POOL_NB, 256>>>(bufA, bat, n);
    k_final<<<1, 128>>>(b2, Wfc, bfc, out);
}

// round 11
// speedup vs baseline: 1.0625x; 1.0625x over previous
#include <cuda_runtime.h>
#include <cuda_fp16.h>
#include <cuda_bf16.h>

#define N_NODES   100000
#define N_EDGES   3200000
#define IN_DIM    128
#define HID       64
#define OUT_DIM   128
#define N_GRAPHS  8
#define SCAN_B    1024
#define WFIX      1048576.0f          // 2^20 fixed-point scale for weights

// ---------------- scratch (static __device__, no allocs) ----------------
__device__ unsigned long long g_pk[N_NODES];            // {count:24 | wsum.20fix:40}
__device__ float g_dinv[N_NODES];
__device__ int   g_cnt_e[N_NODES];
__device__ int   g_incl[N_NODES];
__device__ int   g_rowptr[N_NODES + 1];
__device__ int   g_bsum[256];
__device__ int   g_epos[N_EDGES];                       // within-row position per edge
__device__ __align__(16) int2  g_edge[N_EDGES];         // {src, (dinv[s]*w) bits}
__device__ __align__(16) __half g_bufH[N_NODES * HID];  // fp16 features for gathers
__device__ __align__(16) float g_bufA[N_NODES * HID];
__device__ __align__(16) float g_bufB[N_NODES * HID];
__device__ float g_pool[N_GRAPHS * HID];
__device__ float g_cnt[N_GRAPHS];

// ---------------- init: packed (count=0, wsum=1.0 for self loop) ----------------
__global__ void k_init0(int n) {
    int i = blockIdx.x * blockDim.x + threadIdx.x;
    if (i < n) g_pk[i] = (unsigned long long)(1u << 20);   // weight 1.0 fixed
    if (i < N_GRAPHS * HID) g_pool[i] = 0.0f;
    if (i < N_GRAPHS) g_cnt[i] = 0.0f;
}

// ---------------- count: 4 edges/thread, ONE packed 64-bit atomic per edge ---------
__global__ void k_count(const int* __restrict__ dst,
                        const float* __restrict__ w, int E) {
    int i0 = (blockIdx.x * blockDim.x + threadIdx.x) * 4;
    if (i0 >= E) return;
    if (i0 + 3 < E) {
        int4   d4 = *(const int4*)(dst + i0);
        float4 w4 = *(const float4*)(w + i0);
        unsigned long long i0v = (1ULL << 40) | (unsigned long long)__float2uint_rn(w4.x * WFIX);
        unsigned long long i1v = (1ULL << 40) | (unsigned long long)__float2uint_rn(w4.y * WFIX);
        unsigned long long i2v = (1ULL << 40) | (unsigned long long)__float2uint_rn(w4.z * WFIX);
        unsigned long long i3v = (1ULL << 40) | (unsigned long long)__float2uint_rn(w4.w * WFIX);
        unsigned long long o0 = atomicAdd(&g_pk[d4.x], i0v);
        unsigned long long o1 = atomicAdd(&g_pk[d4.y], i1v);
        unsigned long long o2 = atomicAdd(&g_pk[d4.z], i2v);
        unsigned long long o3 = atomicAdd(&g_pk[d4.w], i3v);
        int4 ep = make_int4((int)(o0 >> 40), (int)(o1 >> 40), (int)(o2 >> 40), (int)(o3 >> 40));
        *(int4*)(g_epos + i0) = ep;
    } else {
        for (int e = i0; e < E; e++) {
            int d = dst[e];
            unsigned long long inc = (1ULL << 40) | (unsigned long long)__float2uint_rn(w[e] * WFIX);
            unsigned long long old = atomicAdd(&g_pk[d], inc);
            g_epos[e] = (int)(old >> 40);
        }
    }
}

// ---------------- scan stage A: unpack pk -> cnt + dinv; inclusive scan ----------------
__global__ void k_scanA(int n) {
    __shared__ int sh[256];
    int base = blockIdx.x * SCAN_B;
    int t = threadIdx.x;
    int v[4]; int s = 0;
#pragma unroll
    for (int j = 0; j < 4; j++) {
        int i = base + t * 4 + j;
        int c = 0;
        if (i < n) {
            unsigned long long pk = g_pk[i];
            c = (int)(pk >> 40);
            float deg = (float)(pk & ((1ULL << 40) - 1)) * (1.0f / WFIX);
            g_dinv[i] = rsqrtf(deg);
            g_cnt_e[i] = c;
        }
        v[j] = c;
        s += c;
    }
    sh[t] = s; __syncthreads();
    for (int off = 1; off < 256; off <<= 1) {
        int x = (t >= off) ? sh[t - off] : 0;
        __syncthreads();
        sh[t] += x;
        __syncthreads();
    }
    int run = sh[t] - s;
#pragma unroll
    for (int j = 0; j < 4; j++) {
        run += v[j];
        int i = base + t * 4 + j;
        if (i < n) g_incl[i] = run;
    }
    if (t == 255) g_bsum[blockIdx.x] = sh[255];
}

// ---------------- scan stage B: exclusive scan of block totals ----------------
__global__ void k_scanB(int nb) {
    __shared__ int sh[128];
    int t = threadIdx.x;
    int v = (t < nb) ? g_bsum[t] : 0;
    sh[t] = v; __syncthreads();
    for (int off = 1; off < 128; off <<= 1) {
        int x = (t >= off) ? sh[t - off] : 0;
        __syncthreads();
        sh[t] += x;
        __syncthreads();
    }
    if (t < nb) g_bsum[t] = sh[t] - v;
}

// ---------------- scan stage C: rowptr = exclusive prefix ----------------
__global__ void k_scanC(int n, int E) {
    int i = blockIdx.x * blockDim.x + threadIdx.x;
    if (i < n) g_rowptr[i] = g_incl[i] - g_cnt_e[i] + g_bsum[i >> 10];
    if (i == 0) g_rowptr[n] = E;
}

// ---------------- fill CSR (by dst): 4 edges/thread, normS = dinv[s]*w ----------
// dinv[d] is factored out of the edge record and applied in the gather epilogue.
__global__ void k_fill(const int* __restrict__ src, const int* __restrict__ dst,
                       const float* __restrict__ w, int E) {
    int i0 = (blockIdx.x * blockDim.x + threadIdx.x) * 4;
    if (i0 >= E) return;
    if (i0 + 3 < E) {
        int4   s4 = *(const int4*)(src + i0);
        int4   d4 = *(const int4*)(dst + i0);
        int4   e4 = *(const int4*)(g_epos + i0);
        float4 w4 = *(const float4*)(w + i0);
        // issue all random loads up front (MLP)
        float ds0 = g_dinv[s4.x], ds1 = g_dinv[s4.y], ds2 = g_dinv[s4.z], ds3 = g_dinv[s4.w];
        int   r0 = g_rowptr[d4.x], r1 = g_rowptr[d4.y], r2 = g_rowptr[d4.z], r3 = g_rowptr[d4.w];
        g_edge[r0 + e4.x] = make_int2(s4.x, __float_as_int(ds0 * w4.x));
        g_edge[r1 + e4.y] = make_int2(s4.y, __float_as_int(ds1 * w4.y));
        g_edge[r2 + e4.z] = make_int2(s4.z, __float_as_int(ds2 * w4.z));
        g_edge[r3 + e4.w] = make_int2(s4.w, __float_as_int(ds3 * w4.w));
    } else {
        for (int e = i0; e < E; e++) {
            int s = src[e], d = dst[e];
            int pos = g_rowptr[d] + g_epos[e];
            g_edge[pos] = make_int2(s, __float_as_int(g_dinv[s] * w[e]));
        }
    }
}

// ---------------- register-tiled GEMM: Y[n x 64] = X'[n x K] @ W[K x 64] ----
// X' = INRELU ? relu(X + b) : X. Output always fp16 (half2-packed).
template <int K, bool INRELU>
__global__ void k_gemm(const float* __restrict__ X, const float* __restrict__ W,
                       const float* __restrict__ bias, __half* __restrict__ Y, int n) {
    __shared__ float Xs[128 * 33];
    __shared__ float Ws[32 * 64];

    int t = threadIdx.x;
    int row0 = blockIdx.x * 128;
    int tx = t & 7;
    int ty = t >> 3;
    int c0 = tx * 8;
    int r0 = ty * 4;

    float acc[4][8];
#pragma unroll
    for (int i = 0; i < 4; i++)
#pragma unroll
        for (int j = 0; j < 8; j++) acc[i][j] = 0.0f;

    for (int kc = 0; kc < K; kc += 32) {
#pragma unroll
        for (int i = t; i < 32 * 64; i += 256) Ws[i] = W[(kc + (i >> 6)) * 64 + (i & 63)];
#pragma unroll
        for (int i = t; i < 128 * 32; i += 256) {
            int r = i >> 5, k = i & 31;
            int gr = row0 + r;
            float v = (gr < n) ? X[gr * K + kc + k] : 0.0f;
            if (INRELU) v = fmaxf(v + __ldg(&bias[kc + k]), 0.0f);
            Xs[r * 33 + k] = v;
        }
        __syncthreads();

#pragma unroll
        for (int k = 0; k < 32; k++) {
            float xv[4];
#pragma unroll
            for (int i = 0; i < 4; i++) xv[i] = Xs[(r0 + i) * 33 + k];
            float4 w0 = *(const float4*)&Ws[k * 64 + c0];
            float4 w1 = *(const float4*)&Ws[k * 64 + c0 + 4];
            float wv[8] = {w0.x, w0.y, w0.z, w0.w, w1.x, w1.y, w1.z, w1.w};
#pragma unroll
            for (int i = 0; i < 4; i++)
#pragma unroll
                for (int j = 0; j < 8; j++) acc[i][j] += xv[i] * wv[j];
        }
        __syncthreads();
    }

#pragma unroll
    for (int i = 0; i < 4; i++) {
        int row = row0 + r0 + i;
        if (row < n) {
            __half2 h[4];
#pragma unroll
            for (int j = 0; j < 4; j++)
                h[j] = __floats2half2_rn(acc[i][2 * j], acc[i][2 * j + 1]);
            *(uint4*)(Y + row * 64 + c0) = *(uint4*)h;
        }
    }
}

// ---------------- gather conv, fp16 H: OUT[d] = dv*(dv*H[d] + sum normS*H[src]) ----
// warp per node: 8 feature lanes (8 halfs = 16B each) x 4 edge slots.
__global__ void k_gather_h(const __half* __restrict__ H, float* __restrict__ OUT, int n) {
    int t = threadIdx.x;
    int fl   = t & 7;             // feature lane: halfs [fl*8, fl*8+8)
    int slot = (t >> 3) & 3;      // edge slot 0..3
    int node = blockIdx.x * 8 + (t >> 5);
    if (node >= n) return;

    const uint4* Hp = (const uint4*)H;   // 8 uint4 per row

    float f[8];
#pragma unroll
    for (int j = 0; j < 8; j++) f[j] = 0.0f;

    float dv = g_dinv[node];
    if (slot == 0) {
        uint4 u = Hp[node * 8 + fl];
        const __half2* hp = (const __half2*)&u;
#pragma unroll
        for (int j = 0; j < 4; j++) {
            float2 v = __half22float2(hp[j]);
            f[2 * j]     = dv * v.x;
            f[2 * j + 1] = dv * v.y;
        }
    }

    int beg = g_rowptr[node], end = g_rowptr[node + 1];
    int e = beg + slot;
    for (; e + 4 < end; e += 8) {
        int2 e0 = g_edge[e];
        int2 e1 = g_edge[e + 4];
        uint4 u0 = Hp[e0.x * 8 + fl];
        uint4 u1 = Hp[e1.x * 8 + fl];
        float n0 = __int_as_float(e0.y);
        float n1 = __int_as_float(e1.y);
        const __half2* h0 = (const __half2*)&u0;
        const __half2* h1 = (const __half2*)&u1;
#pragma unroll
        for (int j = 0; j < 4; j++) {
            float2 v0 = __half22float2(h0[j]);
            float2 v1 = __half22float2(h1[j]);
            f[2 * j]     += n0 * v0.x + n1 * v1.x;
            f[2 * j + 1] += n0 * v0.y + n1 * v1.y;
        }
    }
    for (; e < end; e += 4) {
        int2 e0 = g_edge[e];
        uint4 u0 = Hp[e0.x * 8 + fl];
        float n0 = __int_as_float(e0.y);
        const __half2* h0 = (const __half2*)&u0;
#pragma unroll
        for (int j = 0; j < 4; j++) {
            float2 v0 = __half22float2(h0[j]);
            f[2 * j]     += n0 * v0.x;
            f[2 * j + 1] += n0 * v0.y;
        }
    }

    // reduce across the 4 edge slots (xor 8, xor 16)
#pragma unroll
    for (int off = 8; off < 32; off <<= 1)
#pragma unroll
        for (int j = 0; j < 8; j++)
            f[j] += __shfl_xor_sync(0xffffffffu, f[j], off);

    if (slot == 0) {
        float4 o0 = {dv * f[0], dv * f[1], dv * f[2], dv * f[3]};
        float4 o1 = {dv * f[4], dv * f[5], dv * f[6], dv * f[7]};
        *(float4*)&OUT[node * 64 + fl * 8]     = o0;
        *(float4*)&OUT[node * 64 + fl * 8 + 4] = o1;
    }
}

// ---------------- pool: two-stage segment sum over batch ids ----------------
#define POOL_NB 512
__global__ void k_pool(const float* __restrict__ AGG,
                       const int* __restrict__ batch, int n) {
    __shared__ float acc[N_GRAPHS][HID];
    __shared__ float scnt[N_GRAPHS];
    for (int i = threadIdx.x; i < N_GRAPHS * HID; i += 256)
        acc[i / HID][i % HID] = 0.f;
    if (threadIdx.x < N_GRAPHS) scnt[threadIdx.x] = 0.f;
    __syncthreads();

    int c  = threadIdx.x & 63;
    int nl = threadIdx.x >> 6;
    int base = blockIdx.x * POOL_NB;
    int lim = min(base + POOL_NB, n);
    for (int i = base + nl; i < lim; i += 4) {
        int b = batch[i];
        atomicAdd(&acc[b][c], AGG[i * 64 + c]);
        if (c == 0) atomicAdd(&scnt[b], 1.0f);
    }
    __syncthreads();
    for (int i = threadIdx.x; i < N_GRAPHS * HID; i += 256)
        atomicAdd(&g_pool[i], acc[i / HID][i % HID]);
    if (threadIdx.x < N_GRAPHS) atomicAdd(&g_cnt[threadIdx.x], scnt[threadIdx.x]);
}

// ---------------- final: out[g][o] = (pool[g]/cnt[g] + b2) @ Wfc + bfc ----------------
__global__ void k_final(const float* __restrict__ b2, const float* __restrict__ Wfc,
                        const float* __restrict__ bfc, float* __restrict__ out) {
    __shared__ float P[N_GRAPHS][HID];
    for (int i = threadIdx.x; i < N_GRAPHS * HID; i += 128) {
        int g = i / HID, c = i % HID;
        float cnt = fmaxf(g_cnt[g], 1.0f);
        P[g][c] = g_pool[i] / cnt + b2[c];
    }
    __syncthreads();
    int o = threadIdx.x;   // 128 threads
    for (int g = 0; g < N_GRAPHS; g++) {
        float s = bfc[o];
#pragma unroll
        for (int c = 0; c < HID; c++)
            s += P[g][c] * Wfc[c * OUT_DIM + o];
        out[g * OUT_DIM + o] = s;
    }
}

// ---------------- conv2 input is fp32 bufB: separate gemm wrapper ----------------
// (gemm template reads fp32 X; both convs' gemms write fp16)

// ---------------- launcher ----------------
extern "C" void kernel_launch(void* const* d_in, const int* in_sizes, int n_in,
                              void* d_out, int out_size) {
    const float* x   = (const float*)d_in[0];
    const int*   ei  = (const int*)d_in[1];     // int64 inputs arrive as int32
    const float* ew  = (const float*)d_in[2];
    const int*   bat = (const int*)d_in[3];
    const float* W1  = (const float*)d_in[4];
    const float* b1  = (const float*)d_in[5];
    const float* W2  = (const float*)d_in[6];
    const float* b2  = (const float*)d_in[7];
    const float* Wfc = (const float*)d_in[8];
    const float* bfc = (const float*)d_in[9];
    float* out = (float*)d_out;

    int n = in_sizes[0] / IN_DIM;      // 100000
    int E = in_sizes[2];               // 3200000
    const int* src = ei;
    const int* dst = ei + E;

    float *bufA, *bufB;
    __half* bufH;
    cudaGetSymbolAddress((void**)&bufA, g_bufA);
    cudaGetSymbolAddress((void**)&bufB, g_bufB);
    cudaGetSymbolAddress((void**)&bufH, g_bufH);

    int nb = (n + SCAN_B - 1) / SCAN_B;           // 98 scan blocks
    int gE4 = (E / 4 + 255) / 256;                // 4-edges-per-thread grids
    int gN = (n + 255) / 256;

    // ---- CSR build (once per launch) ----
    k_init0<<<gN, 256>>>(n);
    k_count<<<gE4, 256>>>(dst, ew, E);
    k_scanA<<<nb, 256>>>(n);
    k_scanB<<<1, 128>>>(nb);
    k_scanC<<<gN, 256>>>(n, E);
    k_fill<<<gE4, 256>>>(src, dst, ew, E);

    // ---- conv1: h1 = x @ W1 -> bufH (fp16) ; agg1 -> bufB (fp32) ----
    k_gemm<IN_DIM, false><<<(n + 127) / 128, 256>>>(x, W1, nullptr, bufH, n);
    k_gather_h<<<(n + 7) / 8, 256>>>(bufH, bufB, n);

    // ---- conv2: h2 = relu(agg1 + b1) @ W2 -> bufH (fp16) ; agg2 -> bufA ----
    k_gemm<HID, true><<<(n + 127) / 128, 256>>>(bufB, W2, b1, bufH, n);
    k_gather_h<<<(n + 7) / 8, 256>>>(bufH, bufA, n);

    // ---- pool (b2 folded into final) + fc ----
    k_pool<<<(n + POOL_NB - 1) / POOL_NB, 256>>>(bufA, bat, n);
    k_final<<<1, 128>>>(b2, Wfc, bfc, out);
}

// round 12
// speedup vs baseline: 1.1591x; 1.0909x over previous
#include <cuda_runtime.h>
#include <cuda_fp16.h>
#include <cuda_bf16.h>

#define N_NODES   100000
#define N_EDGES   3200000
#define IN_DIM    128
#define HID       64
#define OUT_DIM   128
#define N_GRAPHS  8
#define WFIX      1048576.0f          // 2^20 fixed-point scale for weights

// ---------------- scratch (static __device__, no allocs) ----------------
__device__ unsigned long long g_pk[N_NODES];            // {count:24 | wsum.20fix:40}
__device__ float g_dinv[N_NODES];
__device__ int   g_cnt_e[N_NODES];
__device__ int   g_rowptr[N_NODES];                     // per-row base (non-ordered)
__device__ int   g_total;
__device__ int   g_epos[N_EDGES];                       // within-row position per edge
__device__ __align__(16) int2  g_edge[N_EDGES];         // {src, (dinv[s]*w) bits}
__device__ __align__(16) __half g_bufH[N_NODES * HID];  // fp16 features for gathers
__device__ __align__(16) float g_bufA[N_NODES * HID];
__device__ __align__(16) float g_bufB[N_NODES * HID];
__device__ float g_pool[N_GRAPHS * HID];
__device__ float g_cnt[N_GRAPHS];

// ---------------- init: packed (count=0, wsum=1.0 self loop); totals ----------------
__global__ void k_init0(int n) {
    int i = blockIdx.x * blockDim.x + threadIdx.x;
    if (i < n) g_pk[i] = (unsigned long long)(1u << 20);   // weight 1.0 fixed
    if (i < N_GRAPHS * HID) g_pool[i] = 0.0f;
    if (i < N_GRAPHS) g_cnt[i] = 0.0f;
    if (i == 0) g_total = 0;
}

// ---------------- FUSED: gemm1 (blocks < GB) || edge count (blocks >= GB) --------
// gemm1: bufH[n x 64] = x[n x 128] @ W1 (fp16 out).
// count: 4 edges/thread, ONE packed 64-bit atomic per edge.
__global__ void k_gemm1_count(const float* __restrict__ X, const float* __restrict__ W,
                              __half* __restrict__ Y,
                              const int* __restrict__ dst, const float* __restrict__ w,
                              int n, int E, int GB) {
    __shared__ float Xs[128 * 33];
    __shared__ float Ws[32 * 64];
    int t = threadIdx.x;

    if (blockIdx.x >= GB) {
        // -------- count role: 4 edges/thread --------
        int i0 = ((blockIdx.x - GB) * 256 + t) * 4;
        if (i0 >= E) return;
        if (i0 + 3 < E) {
            int4   d4 = *(const int4*)(dst + i0);
            float4 w4 = *(const float4*)(w + i0);
            unsigned long long i0v = (1ULL << 40) | (unsigned long long)__float2uint_rn(w4.x * WFIX);
            unsigned long long i1v = (1ULL << 40) | (unsigned long long)__float2uint_rn(w4.y * WFIX);
            unsigned long long i2v = (1ULL << 40) | (unsigned long long)__float2uint_rn(w4.z * WFIX);
            unsigned long long i3v = (1ULL << 40) | (unsigned long long)__float2uint_rn(w4.w * WFIX);
            unsigned long long o0 = atomicAdd(&g_pk[d4.x], i0v);
            unsigned long long o1 = atomicAdd(&g_pk[d4.y], i1v);
            unsigned long long o2 = atomicAdd(&g_pk[d4.z], i2v);
            unsigned long long o3 = atomicAdd(&g_pk[d4.w], i3v);
            *(int4*)(g_epos + i0) = make_int4((int)(o0 >> 40), (int)(o1 >> 40),
                                              (int)(o2 >> 40), (int)(o3 >> 40));
        } else {
            for (int e = i0; e < E; e++) {
                int d = dst[e];
                unsigned long long inc = (1ULL << 40) | (unsigned long long)__float2uint_rn(w[e] * WFIX);
                unsigned long long old = atomicAdd(&g_pk[d], inc);
                g_epos[e] = (int)(old >> 40);
            }
        }
        return;
    }

    // -------- gemm role (K = IN_DIM = 128) --------
    int row0 = blockIdx.x * 128;
    int tx = t & 7;
    int ty = t >> 3;
    int c0 = tx * 8;
    int r0 = ty * 4;

    float acc[4][8];
#pragma unroll
    for (int i = 0; i < 4; i++)
#pragma unroll
        for (int j = 0; j < 8; j++) acc[i][j] = 0.0f;

    for (int kc = 0; kc < IN_DIM; kc += 32) {
#pragma unroll
        for (int i = t; i < 32 * 64; i += 256) Ws[i] = W[(kc + (i >> 6)) * 64 + (i & 63)];
#pragma unroll
        for (int i = t; i < 128 * 32; i += 256) {
            int r = i >> 5, k = i & 31;
            int gr = row0 + r;
            Xs[r * 33 + k] = (gr < n) ? X[gr * IN_DIM + kc + k] : 0.0f;
        }
        __syncthreads();

#pragma unroll
        for (int k = 0; k < 32; k++) {
            float xv[4];
#pragma unroll
            for (int i = 0; i < 4; i++) xv[i] = Xs[(r0 + i) * 33 + k];
            float4 w0 = *(const float4*)&Ws[k * 64 + c0];
            float4 w1 = *(const float4*)&Ws[k * 64 + c0 + 4];
            float wv[8] = {w0.x, w0.y, w0.z, w0.w, w1.x, w1.y, w1.z, w1.w};
#pragma unroll
            for (int i = 0; i < 4; i++)
#pragma unroll
                for (int j = 0; j < 8; j++) acc[i][j] += xv[i] * wv[j];
        }
        __syncthreads();
    }

#pragma unroll
    for (int i = 0; i < 4; i++) {
        int row = row0 + r0 + i;
        if (row < n) {
            __half2 h[4];
#pragma unroll
            for (int j = 0; j < 4; j++)
                h[j] = __floats2half2_rn(acc[i][2 * j], acc[i][2 * j + 1]);
            *(uint4*)(Y + row * 64 + c0) = *(uint4*)h;
        }
    }
}

// ---------------- fused scan: unpack pk -> dinv/cnt; rowptr via atomic base ----------
// Row bases are block-ordered but not node-ordered — CSR only needs contiguity.
__global__ void k_scan(int n) {
    __shared__ int sh[256];
    __shared__ int base_sh;
    int t = threadIdx.x;
    int i0 = blockIdx.x * 1024 + t * 4;
    int v[4]; int s = 0;
#pragma unroll
    for (int j = 0; j < 4; j++) {
        int i = i0 + j;
        int c = 0;
        if (i < n) {
            unsigned long long pk = g_pk[i];
            c = (int)(pk >> 40);
            float deg = (float)(pk & ((1ULL << 40) - 1)) * (1.0f / WFIX);
            g_dinv[i] = rsqrtf(deg);
            g_cnt_e[i] = c;
        }
        v[j] = c;
        s += c;
    }
    sh[t] = s; __syncthreads();
    for (int off = 1; off < 256; off <<= 1) {
        int x = (t >= off) ? sh[t - off] : 0;
        __syncthreads();
        sh[t] += x;
        __syncthreads();
    }
    if (t == 255) base_sh = atomicAdd(&g_total, sh[255]);
    __syncthreads();
    int run = base_sh + sh[t] - s;      // exclusive prefix for this thread's first node
#pragma unroll
    for (int j = 0; j < 4; j++) {
        int i = i0 + j;
        if (i < n) g_rowptr[i] = run;
        run += v[j];
    }
}

// ---------------- fill CSR (by dst): 4 edges/thread, normS = dinv[s]*w ----------
__global__ void k_fill(const int* __restrict__ src, const int* __restrict__ dst,
                       const float* __restrict__ w, int E) {
    int i0 = (blockIdx.x * blockDim.x + threadIdx.x) * 4;
    if (i0 >= E) return;
    if (i0 + 3 < E) {
        int4   s4 = *(const int4*)(src + i0);
        int4   d4 = *(const int4*)(dst + i0);
        int4   e4 = *(const int4*)(g_epos + i0);
        float4 w4 = *(const float4*)(w + i0);
        float ds0 = g_dinv[s4.x], ds1 = g_dinv[s4.y], ds2 = g_dinv[s4.z], ds3 = g_dinv[s4.w];
        int   r0 = g_rowptr[d4.x], r1 = g_rowptr[d4.y], r2 = g_rowptr[d4.z], r3 = g_rowptr[d4.w];
        g_edge[r0 + e4.x] = make_int2(s4.x, __float_as_int(ds0 * w4.x));
        g_edge[r1 + e4.y] = make_int2(s4.y, __float_as_int(ds1 * w4.y));
        g_edge[r2 + e4.z] = make_int2(s4.z, __float_as_int(ds2 * w4.z));
        g_edge[r3 + e4.w] = make_int2(s4.w, __float_as_int(ds3 * w4.w));
    } else {
        for (int e = i0; e < E; e++) {
            int s = src[e], d = dst[e];
            int pos = g_rowptr[d] + g_epos[e];
            g_edge[pos] = make_int2(s, __float_as_int(g_dinv[s] * w[e]));
        }
    }
}

// ---------------- register-tiled GEMM (conv2): relu(X+b) in, fp16 out ----------------
__global__ void k_gemm2(const float* __restrict__ X, const float* __restrict__ W,
                        const float* __restrict__ bias, __half* __restrict__ Y, int n) {
    __shared__ float Xs[128 * 33];
    __shared__ float Ws[32 * 64];

    int t = threadIdx.x;
    int row0 = blockIdx.x * 128;
    int tx = t & 7;
    int ty = t >> 3;
    int c0 = tx * 8;
    int r0 = ty * 4;

    float acc[4][8];
#pragma unroll
    for (int i = 0; i < 4; i++)
#pragma unroll
        for (int j = 0; j < 8; j++) acc[i][j] = 0.0f;

    for (int kc = 0; kc < HID; kc += 32) {
#pragma unroll
        for (int i = t; i < 32 * 64; i += 256) Ws[i] = W[(kc + (i >> 6)) * 64 + (i & 63)];
#pragma unroll
        for (int i = t; i < 128 * 32; i += 256) {
            int r = i >> 5, k = i & 31;
            int gr = row0 + r;
            float v = (gr < n) ? X[gr * HID + kc + k] : 0.0f;
            v = fmaxf(v + __ldg(&bias[kc + k]), 0.0f);
            Xs[r * 33 + k] = v;
        }
        __syncthreads();

#pragma unroll
        for (int k = 0; k < 32; k++) {
            float xv[4];
#pragma unroll
            for (int i = 0; i < 4; i++) xv[i] = Xs[(r0 + i) * 33 + k];
            float4 w0 = *(const float4*)&Ws[k * 64 + c0];
            float4 w1 = *(const float4*)&Ws[k * 64 + c0 + 4];
            float wv[8] = {w0.x, w0.y, w0.z, w0.w, w1.x, w1.y, w1.z, w1.w};
#pragma unroll
            for (int i = 0; i < 4; i++)
#pragma unroll
                for (int j = 0; j < 8; j++) acc[i][j] += xv[i] * wv[j];
        }
        __syncthreads();
    }

#pragma unroll
    for (int i = 0; i < 4; i++) {
        int row = row0 + r0 + i;
        if (row < n) {
            __half2 h[4];
#pragma unroll
            for (int j = 0; j < 4; j++)
                h[j] = __floats2half2_rn(acc[i][2 * j], acc[i][2 * j + 1]);
            *(uint4*)(Y + row * 64 + c0) = *(uint4*)h;
        }
    }
}

// ---------------- gather conv, fp16 H: OUT[d] = dv*(dv*H[d] + sum normS*H[src]) ----
// warp per node: 8 feature lanes (16B each) x 4 edge slots; end = rowptr + cnt.
__global__ void k_gather_h(const __half* __restrict__ H, float* __restrict__ OUT, int n) {
    int t = threadIdx.x;
    int fl   = t & 7;
    int slot = (t >> 3) & 3;
    int node = blockIdx.x * 8 + (t >> 5);
    if (node >= n) return;

    const uint4* Hp = (const uint4*)H;

    float f[8];
#pragma unroll
    for (int j = 0; j < 8; j++) f[j] = 0.0f;

    float dv = g_dinv[node];
    if (slot == 0) {
        uint4 u = Hp[node * 8 + fl];
        const __half2* hp = (const __half2*)&u;
#pragma unroll
        for (int j = 0; j < 4; j++) {
            float2 v = __half22float2(hp[j]);
            f[2 * j]     = dv * v.x;
            f[2 * j + 1] = dv * v.y;
        }
    }

    int beg = g_rowptr[node];
    int end = beg + g_cnt_e[node];
    int e = beg + slot;
    for (; e + 4 < end; e += 8) {
        int2 e0 = g_edge[e];
        int2 e1 = g_edge[e + 4];
        uint4 u0 = Hp[e0.x * 8 + fl];
        uint4 u1 = Hp[e1.x * 8 + fl];
        float n0 = __int_as_float(e0.y);
        float n1 = __int_as_float(e1.y);
        const __half2* h0 = (const __half2*)&u0;
        const __half2* h1 = (const __half2*)&u1;
#pragma unroll
        for (int j = 0; j < 4; j++) {
            float2 v0 = __half22float2(h0[j]);
            float2 v1 = __half22float2(h1[j]);
            f[2 * j]     += n0 * v0.x + n1 * v1.x;
            f[2 * j + 1] += n0 * v0.y + n1 * v1.y;
        }
    }
    for (; e < end; e += 4) {
        int2 e0 = g_edge[e];
        uint4 u0 = Hp[e0.x * 8 + fl];
        float n0 = __int_as_float(e0.y);
        const __half2* h0 = (const __half2*)&u0;
#pragma unroll
        for (int j = 0; j < 4; j++) {
            float2 v0 = __half22float2(h0[j]);
            f[2 * j]     += n0 * v0.x;
            f[2 * j + 1] += n0 * v0.y;
        }
    }

#pragma unroll
    for (int off = 8; off < 32; off <<= 1)
#pragma unroll
        for (int j = 0; j < 8; j++)
            f[j] += __shfl_xor_sync(0xffffffffu, f[j], off);

    if (slot == 0) {
        float4 o0 = {dv * f[0], dv * f[1], dv * f[2], dv * f[3]};
        float4 o1 = {dv * f[4], dv * f[5], dv * f[6], dv * f[7]};
        *(float4*)&OUT[node * 64 + fl * 8]     = o0;
        *(float4*)&OUT[node * 64 + fl * 8 + 4] = o1;
    }
}

// ---------------- pool: two-stage segment sum over batch ids ----------------
#define POOL_NB 512
__global__ void k_pool(const float* __restrict__ AGG,
                       const int* __restrict__ batch, int n) {
    __shared__ float acc[N_GRAPHS][HID];
    __shared__ float scnt[N_GRAPHS];
    for (int i = threadIdx.x; i < N_GRAPHS * HID; i += 256)
        acc[i / HID][i % HID] = 0.f;
    if (threadIdx.x < N_GRAPHS) scnt[threadIdx.x] = 0.f;
    __syncthreads();

    int c  = threadIdx.x & 63;
    int nl = threadIdx.x >> 6;
    int base = blockIdx.x * POOL_NB;
    int lim = min(base + POOL_NB, n);
    for (int i = base + nl; i < lim; i += 4) {
        int b = batch[i];
        atomicAdd(&acc[b][c], AGG[i * 64 + c]);
        if (c == 0) atomicAdd(&scnt[b], 1.0f);
    }
    __syncthreads();
    for (int i = threadIdx.x; i < N_GRAPHS * HID; i += 256)
        atomicAdd(&g_pool[i], acc[i / HID][i % HID]);
    if (threadIdx.x < N_GRAPHS) atomicAdd(&g_cnt[threadIdx.x], scnt[threadIdx.x]);
}

// ---------------- final: out[g][o] = (pool[g]/cnt[g] + b2) @ Wfc + bfc ----------------
__global__ void k_final(const float* __restrict__ b2, const float* __restrict__ Wfc,
                        const float* __restrict__ bfc, float* __restrict__ out) {
    __shared__ float P[N_GRAPHS][HID];
    for (int i = threadIdx.x; i < N_GRAPHS * HID; i += 128) {
        int g = i / HID, c = i % HID;
        float cnt = fmaxf(g_cnt[g], 1.0f);
        P[g][c] = g_pool[i] / cnt + b2[c];
    }
    __syncthreads();
    int o = threadIdx.x;   // 128 threads
    for (int g = 0; g < N_GRAPHS; g++) {
        float s = bfc[o];
#pragma unroll
        for (int c = 0; c < HID; c++)
            s += P[g][c] * Wfc[c * OUT_DIM + o];
        out[g * OUT_DIM + o] = s;
    }
}

// ---------------- launcher ----------------
extern "C" void kernel_launch(void* const* d_in, const int* in_sizes, int n_in,
                              void* d_out, int out_size) {
    const float* x   = (const float*)d_in[0];
    const int*   ei  = (const int*)d_in[1];     // int64 inputs arrive as int32
    const float* ew  = (const float*)d_in[2];
    const int*   bat = (const int*)d_in[3];
    const float* W1  = (const float*)d_in[4];
    const float* b1  = (const float*)d_in[5];
    const float* W2  = (const float*)d_in[6];
    const float* b2  = (const float*)d_in[7];
    const float* Wfc = (const float*)d_in[8];
    const float* bfc = (const float*)d_in[9];
    float* out = (float*)d_out;

    int n = in_sizes[0] / IN_DIM;      // 100000
    int E = in_sizes[2];               // 3200000
    const int* src = ei;
    const int* dst = ei + E;

    float *bufA, *bufB;
    __half* bufH;
    cudaGetSymbolAddress((void**)&bufA, g_bufA);
    cudaGetSymbolAddress((void**)&bufB, g_bufB);
    cudaGetSymbolAddress((void**)&bufH, g_bufH);

    int gE4 = (E / 4 + 255) / 256;                // 3125 count/fill blocks
    int gN  = (n + 255) / 256;
    int GB  = (n + 127) / 128;                    // 782 gemm blocks
    int nsb = (n + 1023) / 1024;                  // 98 scan blocks

    // ---- init; fused gemm1 || count; fused scan; fill ----
    k_init0<<<gN, 256>>>(n);
    k_gemm1_count<<<GB + gE4, 256>>>(x, W1, bufH, dst, ew, n, E, GB);
    k_scan<<<nsb, 256>>>(n);
    k_fill<<<gE4, 256>>>(src, dst, ew, E);

    // ---- conv1 gather: agg1 -> bufB (fp32) ----
    k_gather_h<<<(n + 7) / 8, 256>>>(bufH, bufB, n);

    // ---- conv2: h2 = relu(agg1 + b1) @ W2 -> bufH (fp16) ; agg2 -> bufA ----
    k_gemm2<<<GB, 256>>>(bufB, W2, b1, bufH, n);
    k_gather_h<<<(n + 7) / 8, 256>>>(bufH, bufA, n);

    // ---- pool (b2 folded into final) + fc ----
    k_pool<<<(n + POOL_NB - 1) / POOL_NB, 256>>>(bufA, bat, n);
    k_final<<<1, 128>>>(b2, Wfc, bfc, out);
}